// round 6
// baseline (speedup 1.0000x reference)
#include <cuda_runtime.h>
#include <cstdint>

#define NMAX 50000
#define EMAX 800000

// ---------------- device scratch ----------------
__device__ __align__(16) int   g_cnt[NMAX];
__device__ __align__(16) int   g_rowptr[NMAX];
__device__ __align__(16) int   g_cursor[NMAX];
__device__ __align__(16) float g_dinv[NMAX];
__device__ __align__(16) int2  g_ew[EMAX];           // {src, bitcast(norm)}
__device__ __align__(16) float g_bufA[NMAX * 64];
__device__ __align__(16) float g_bufB[NMAX * 64];
__device__ __align__(16) float g_bufC[NMAX * 64];

__device__ __forceinline__ float* bufptr(int s) {
    return (s == 0) ? g_bufA : ((s == 1) ? g_bufB : g_bufC);
}

// ---------------- static streams/events ----------------
static cudaStream_t g_s1;
static cudaEvent_t  g_ef, g_ej;
static struct _StreamInit {
    _StreamInit() {
        cudaStreamCreateWithFlags(&g_s1, cudaStreamNonBlocking);
        cudaEventCreateWithFlags(&g_ef, cudaEventDisableTiming);
        cudaEventCreateWithFlags(&g_ej, cudaEventDisableTiming);
    }
} _stream_init;

// ---------------- CSR build ----------------
__global__ void k_zero(int n4) {
    int i = blockIdx.x * blockDim.x + threadIdx.x;
    if (i < n4) reinterpret_cast<int4*>(g_cnt)[i] = make_int4(0, 0, 0, 0);
}

__global__ void k_hist(const int* __restrict__ ei, int E, int n) {
    int i = blockIdx.x * blockDim.x + threadIdx.x;
    if (i < E) {
        int d = ei[E + i];
        if ((unsigned)d < (unsigned)n) atomicAdd(&g_cnt[d], 1);
    }
}

__global__ void k_scan(int n) {
    __shared__ int ss[1024];
    const int t = threadIdx.x;
    const int chunk = (n + 1023) / 1024;
    const int start = t * chunk;
    const int end = min(start + chunk, n);
    int s = 0;
    for (int i = start; i < end; i++) s += g_cnt[i];
    ss[t] = s;
    __syncthreads();
    for (int off = 1; off < 1024; off <<= 1) {
        int v = (t >= off) ? ss[t - off] : 0;
        __syncthreads();
        ss[t] += v;
        __syncthreads();
    }
    int run = ss[t] - s;
    for (int i = start; i < end; i++) {
        int c = g_cnt[i];
        g_rowptr[i] = run;
        g_cursor[i] = run;
        g_dinv[i] = rsqrtf((float)(c + 1));
        run += c;
    }
}

__global__ void k_scatter(const int* __restrict__ ei, int E, int n) {
    int i = blockIdx.x * blockDim.x + threadIdx.x;
    if (i < E) {
        int s = ei[i];
        int d = ei[E + i];
        if ((unsigned)s < (unsigned)n && (unsigned)d < (unsigned)n) {
            int pos = atomicAdd(&g_cursor[d], 1);
            g_ew[pos] = make_int2(s, __float_as_int(g_dinv[s] * g_dinv[d]));
        }
    }
}

// ---------------- dual-output GEMM: [outA|outB] = X @ [Wa|Wb] ----------------
template <int K, int NC>
__global__ __launch_bounds__(256) void k_gemm_dual(
    const float* __restrict__ Xext, int xsel,
    const float* __restrict__ Wa, const float* __restrict__ Wb,
    int oselA, int oselB, int n)
{
    constexpr int RB  = 128;
    constexpr int KC  = 32;
    constexpr int RBP = RB + 4;
    constexpr int HALF = NC / 2;
    constexpr int TX  = NC / 8;
    constexpr int TY  = 256 / TX;
    constexpr int RPT = RB / TY;

    __shared__ __align__(16) float Wsm[KC][NC];
    __shared__ __align__(16) float XsmT[KC][RBP];

    const float* X = (xsel >= 0) ? bufptr(xsel) : Xext;
    float* outA = bufptr(oselA);
    float* outB = bufptr(oselB);

    const int t = threadIdx.x;
    const int row0 = blockIdx.x * RB;
    const int tx = t % TX;
    const int ty = t / TX;

    float acc[RPT][8];
#pragma unroll
    for (int r = 0; r < RPT; r++)
#pragma unroll
        for (int c = 0; c < 8; c++) acc[r][c] = 0.f;

    for (int kc = 0; kc < K; kc += KC) {
        for (int idx = t; idx < KC * HALF; idx += 256) {
            int k = idx / HALF, j = idx % HALF;
            Wsm[k][j]        = Wa[(size_t)(kc + k) * HALF + j];
            Wsm[k][HALF + j] = Wb[(size_t)(kc + k) * HALF + j];
        }
        for (int idx = t; idx < RB * (KC / 4); idx += 256) {
            int c4 = idx % (KC / 4);
            int r  = idx / (KC / 4);
            float4 v = make_float4(0.f, 0.f, 0.f, 0.f);
            int row = row0 + r;
            if (row < n) v = *reinterpret_cast<const float4*>(X + (size_t)row * K + kc + c4 * 4);
            XsmT[c4 * 4 + 0][r] = v.x;
            XsmT[c4 * 4 + 1][r] = v.y;
            XsmT[c4 * 4 + 2][r] = v.z;
            XsmT[c4 * 4 + 3][r] = v.w;
        }
        __syncthreads();

#pragma unroll
        for (int k = 0; k < KC; k++) {
            float w[8];
            *reinterpret_cast<float4*>(&w[0]) = *reinterpret_cast<const float4*>(&Wsm[k][tx * 8]);
            *reinterpret_cast<float4*>(&w[4]) = *reinterpret_cast<const float4*>(&Wsm[k][tx * 8 + 4]);
            float xr[RPT];
#pragma unroll
            for (int rr = 0; rr < RPT / 4; rr++)
                *reinterpret_cast<float4*>(&xr[rr * 4]) =
                    *reinterpret_cast<const float4*>(&XsmT[k][ty * RPT + rr * 4]);
#pragma unroll
            for (int r = 0; r < RPT; r++)
#pragma unroll
                for (int c = 0; c < 8; c++)
                    acc[r][c] = fmaf(xr[r], w[c], acc[r][c]);
        }
        __syncthreads();
    }

    const int c0 = tx * 8;
#pragma unroll
    for (int r = 0; r < RPT; r++) {
        int row = row0 + ty * RPT + r;
        if (row < n) {
            float4 v0 = make_float4(acc[r][0], acc[r][1], acc[r][2], acc[r][3]);
            float4 v1 = make_float4(acc[r][4], acc[r][5], acc[r][6], acc[r][7]);
            if (c0 < HALF) {
                *reinterpret_cast<float4*>(outA + (size_t)row * HALF + c0)     = v0;
                *reinterpret_cast<float4*>(outA + (size_t)row * HALF + c0 + 4) = v1;
            } else {
                *reinterpret_cast<float4*>(outB + (size_t)row * HALF + c0 - HALF)     = v0;
                *reinterpret_cast<float4*>(outB + (size_t)row * HALF + c0 - HALF + 4) = v1;
            }
        }
    }
}

// ---------------- propagation, float4 lanes, MLP-8 edge pipeline ----------------
template <int C, bool RELUB>
__global__ __launch_bounds__(256) void k_prop(
    int hsel, const float* __restrict__ bias, int othersel, int outsel, int n)
{
    constexpr int L = C / 4;
    const int tid = blockIdx.x * blockDim.x + threadIdx.x;
    const int node = tid / L;
    const int l = threadIdx.x & (L - 1);
    if (node >= n) return;

    const float* __restrict__ h = bufptr(hsel);
    float* __restrict__ out = bufptr(outsel);

    const float dv = g_dinv[node];
    const float sw = dv * dv;
    const int rs = g_rowptr[node];
    const int re = rs + g_cnt[node];

    // pre-issue epilogue operand + self row (overlaps edge chain)
    float4 epi;
    if (RELUB) epi = *reinterpret_cast<const float4*>(bias + l * 4);
    else       epi = *reinterpret_cast<const float4*>(bufptr(othersel) + (size_t)node * C + l * 4);

    float4 s = *reinterpret_cast<const float4*>(h + (size_t)node * C + l * 4);
    float4 a = make_float4(sw * s.x, sw * s.y, sw * s.z, sw * s.w);

    int e = rs;
    // align to even index for int4 (2-edge) loads
    if ((e & 1) && e < re) {
        int2 we = g_ew[e];
        float wv = __int_as_float(we.y);
        float4 hv = *reinterpret_cast<const float4*>(h + (size_t)we.x * C + l * 4);
        a.x = fmaf(wv, hv.x, a.x); a.y = fmaf(wv, hv.y, a.y);
        a.z = fmaf(wv, hv.z, a.z); a.w = fmaf(wv, hv.w, a.w);
        e++;
    }
    // 8 edges per iteration: 4x int4 edge loads, 8 gathers in flight
    for (; e + 8 <= re; e += 8) {
        int4 p0 = *reinterpret_cast<const int4*>(&g_ew[e]);
        int4 p1 = *reinterpret_cast<const int4*>(&g_ew[e + 2]);
        int4 p2 = *reinterpret_cast<const int4*>(&g_ew[e + 4]);
        int4 p3 = *reinterpret_cast<const int4*>(&g_ew[e + 6]);
        const float4* g0 = reinterpret_cast<const float4*>(h + (size_t)p0.x * C + l * 4);
        const float4* g1 = reinterpret_cast<const float4*>(h + (size_t)p0.z * C + l * 4);
        const float4* g2 = reinterpret_cast<const float4*>(h + (size_t)p1.x * C + l * 4);
        const float4* g3 = reinterpret_cast<const float4*>(h + (size_t)p1.z * C + l * 4);
        const float4* g4 = reinterpret_cast<const float4*>(h + (size_t)p2.x * C + l * 4);
        const float4* g5 = reinterpret_cast<const float4*>(h + (size_t)p2.z * C + l * 4);
        const float4* g6 = reinterpret_cast<const float4*>(h + (size_t)p3.x * C + l * 4);
        const float4* g7 = reinterpret_cast<const float4*>(h + (size_t)p3.z * C + l * 4);
        float4 h0 = *g0, h1 = *g1, h2 = *g2, h3 = *g3;
        float4 h4 = *g4, h5 = *g5, h6 = *g6, h7 = *g7;
        float f0 = __int_as_float(p0.y), f1 = __int_as_float(p0.w);
        float f2 = __int_as_float(p1.y), f3 = __int_as_float(p1.w);
        float f4 = __int_as_float(p2.y), f5 = __int_as_float(p2.w);
        float f6 = __int_as_float(p3.y), f7 = __int_as_float(p3.w);
        a.x = fmaf(f0, h0.x, a.x); a.y = fmaf(f0, h0.y, a.y); a.z = fmaf(f0, h0.z, a.z); a.w = fmaf(f0, h0.w, a.w);
        a.x = fmaf(f1, h1.x, a.x); a.y = fmaf(f1, h1.y, a.y); a.z = fmaf(f1, h1.z, a.z); a.w = fmaf(f1, h1.w, a.w);
        a.x = fmaf(f2, h2.x, a.x); a.y = fmaf(f2, h2.y, a.y); a.z = fmaf(f2, h2.z, a.z); a.w = fmaf(f2, h2.w, a.w);
        a.x = fmaf(f3, h3.x, a.x); a.y = fmaf(f3, h3.y, a.y); a.z = fmaf(f3, h3.z, a.z); a.w = fmaf(f3, h3.w, a.w);
        a.x = fmaf(f4, h4.x, a.x); a.y = fmaf(f4, h4.y, a.y); a.z = fmaf(f4, h4.z, a.z); a.w = fmaf(f4, h4.w, a.w);
        a.x = fmaf(f5, h5.x, a.x); a.y = fmaf(f5, h5.y, a.y); a.z = fmaf(f5, h5.z, a.z); a.w = fmaf(f5, h5.w, a.w);
        a.x = fmaf(f6, h6.x, a.x); a.y = fmaf(f6, h6.y, a.y); a.z = fmaf(f6, h6.z, a.z); a.w = fmaf(f6, h6.w, a.w);
        a.x = fmaf(f7, h7.x, a.x); a.y = fmaf(f7, h7.y, a.y); a.z = fmaf(f7, h7.z, a.z); a.w = fmaf(f7, h7.w, a.w);
    }
    for (; e + 2 <= re; e += 2) {
        int4 p = *reinterpret_cast<const int4*>(&g_ew[e]);
        float4 h0 = *reinterpret_cast<const float4*>(h + (size_t)p.x * C + l * 4);
        float4 h1 = *reinterpret_cast<const float4*>(h + (size_t)p.z * C + l * 4);
        float f0 = __int_as_float(p.y), f1 = __int_as_float(p.w);
        a.x = fmaf(f0, h0.x, a.x); a.y = fmaf(f0, h0.y, a.y); a.z = fmaf(f0, h0.z, a.z); a.w = fmaf(f0, h0.w, a.w);
        a.x = fmaf(f1, h1.x, a.x); a.y = fmaf(f1, h1.y, a.y); a.z = fmaf(f1, h1.z, a.z); a.w = fmaf(f1, h1.w, a.w);
    }
    if (e < re) {
        int2 we = g_ew[e];
        float wv = __int_as_float(we.y);
        float4 hv = *reinterpret_cast<const float4*>(h + (size_t)we.x * C + l * 4);
        a.x = fmaf(wv, hv.x, a.x); a.y = fmaf(wv, hv.y, a.y);
        a.z = fmaf(wv, hv.z, a.z); a.w = fmaf(wv, hv.w, a.w);
    }

    if (RELUB) {
        a.x = fmaxf(a.x + epi.x, 0.f); a.y = fmaxf(a.y + epi.y, 0.f);
        a.z = fmaxf(a.z + epi.z, 0.f); a.w = fmaxf(a.w + epi.w, 0.f);
    } else {
        a.x += epi.x; a.y += epi.y; a.z += epi.z; a.w += epi.w;
    }
    *reinterpret_cast<float4*>(out + (size_t)node * C + l * 4) = a;
}

// ---------------- fused: h2 = relu(P(A)+b2) -> heads -> out ----------------
__global__ __launch_bounds__(256) void k_prop_heads(
    int hsel, const float* __restrict__ b2,
    const float* __restrict__ Wp1, const float* __restrict__ bp1,
    const float* __restrict__ Wp2, const float* __restrict__ bp2,
    const float* __restrict__ Wc1, const float* __restrict__ bc1,
    const float* __restrict__ Wc2, const float* __restrict__ bc2,
    float* __restrict__ out, int n)
{
    __shared__ float sWp1[32 * 32], sWp2[32 * 32], sWc1[32 * 16], sWc2[16 * 2];
    __shared__ float sbp1[32], sbp2[32], sbc1[16], sbc2[2];
    const int t = threadIdx.x;
    for (int i = t; i < 1024; i += 256) { sWp1[i] = Wp1[i]; sWp2[i] = Wp2[i]; }
    for (int i = t; i < 512; i += 256) sWc1[i] = Wc1[i];
    if (t < 32) { sWc2[t] = Wc2[t]; sbp1[t] = bp1[t]; sbp2[t] = bp2[t]; }
    if (t < 16) sbc1[t] = bc1[t];
    if (t < 2) sbc2[t] = bc2[t];
    __syncthreads();

    const float* __restrict__ h = bufptr(hsel);
    const int node = (blockIdx.x * blockDim.x + t) >> 5;
    const int lane = t & 31;
    if (node >= n) return;

    const float dv = g_dinv[node];
    const float sw = dv * dv;
    const int rs = g_rowptr[node];
    const int re = rs + g_cnt[node];

    float acc = sw * h[(size_t)node * 32 + lane];
    int e = rs;
    if ((e & 1) && e < re) {
        int2 we = g_ew[e];
        acc = fmaf(__int_as_float(we.y), h[(size_t)we.x * 32 + lane], acc);
        e++;
    }
    for (; e + 8 <= re; e += 8) {
        int4 p0 = *reinterpret_cast<const int4*>(&g_ew[e]);
        int4 p1 = *reinterpret_cast<const int4*>(&g_ew[e + 2]);
        int4 p2 = *reinterpret_cast<const int4*>(&g_ew[e + 4]);
        int4 p3 = *reinterpret_cast<const int4*>(&g_ew[e + 6]);
        float h0 = h[(size_t)p0.x * 32 + lane];
        float h1 = h[(size_t)p0.z * 32 + lane];
        float h2 = h[(size_t)p1.x * 32 + lane];
        float h3 = h[(size_t)p1.z * 32 + lane];
        float h4 = h[(size_t)p2.x * 32 + lane];
        float h5 = h[(size_t)p2.z * 32 + lane];
        float h6 = h[(size_t)p3.x * 32 + lane];
        float h7 = h[(size_t)p3.z * 32 + lane];
        acc = fmaf(__int_as_float(p0.y), h0, acc);
        acc = fmaf(__int_as_float(p0.w), h1, acc);
        acc = fmaf(__int_as_float(p1.y), h2, acc);
        acc = fmaf(__int_as_float(p1.w), h3, acc);
        acc = fmaf(__int_as_float(p2.y), h4, acc);
        acc = fmaf(__int_as_float(p2.w), h5, acc);
        acc = fmaf(__int_as_float(p3.y), h6, acc);
        acc = fmaf(__int_as_float(p3.w), h7, acc);
    }
    for (; e + 2 <= re; e += 2) {
        int4 p = *reinterpret_cast<const int4*>(&g_ew[e]);
        acc = fmaf(__int_as_float(p.y), h[(size_t)p.x * 32 + lane], acc);
        acc = fmaf(__int_as_float(p.w), h[(size_t)p.z * 32 + lane], acc);
    }
    if (e < re) {
        int2 we = g_ew[e];
        acc = fmaf(__int_as_float(we.y), h[(size_t)we.x * 32 + lane], acc);
    }
    const float hv = fmaxf(acc + b2[lane], 0.f);

    float t1 = sbp1[lane];
#pragma unroll
    for (int k = 0; k < 32; k++)
        t1 = fmaf(__shfl_sync(0xffffffffu, hv, k), sWp1[k * 32 + lane], t1);
    t1 = fmaxf(t1, 0.f);

    float z = sbp2[lane];
#pragma unroll
    for (int k = 0; k < 32; k++)
        z = fmaf(__shfl_sync(0xffffffffu, t1, k), sWp2[k * 32 + lane], z);
    out[(size_t)n * 2 + (size_t)node * 32 + lane] = z;

    float tc = sbc1[lane & 15];
#pragma unroll
    for (int k = 0; k < 32; k++)
        tc = fmaf(__shfl_sync(0xffffffffu, hv, k), sWc1[k * 16 + (lane & 15)], tc);
    tc = fmaxf(tc, 0.f);

    float c0 = 0.f, c1 = 0.f;
#pragma unroll
    for (int k = 0; k < 16; k++) {
        float v = __shfl_sync(0xffffffffu, tc, k);
        c0 = fmaf(v, sWc2[k * 2 + 0], c0);
        c1 = fmaf(v, sWc2[k * 2 + 1], c1);
    }
    if (lane == 0) {
        out[(size_t)node * 2 + 0] = c0 + sbc2[0];
        out[(size_t)node * 2 + 1] = c1 + sbc2[1];
    }
}

// ---------------- launch ----------------
extern "C" void kernel_launch(void* const* d_in, const int* in_sizes, int n_in,
                              void* d_out, int out_size)
{
    const float* x  = (const float*)d_in[0];
    const int*   ei = (const int*)d_in[1];
    const float* W1_1 = (const float*)d_in[2];
    const float* W1_2 = (const float*)d_in[3];
    const float* b1   = (const float*)d_in[4];
    const float* W2_1 = (const float*)d_in[5];
    const float* W2_2 = (const float*)d_in[6];
    const float* b2   = (const float*)d_in[7];
    const float* Wp1  = (const float*)d_in[8];
    const float* bp1  = (const float*)d_in[9];
    const float* Wp2  = (const float*)d_in[10];
    const float* bp2  = (const float*)d_in[11];
    const float* Wc1  = (const float*)d_in[12];
    const float* bc1  = (const float*)d_in[13];
    const float* Wc2  = (const float*)d_in[14];
    const float* bc2  = (const float*)d_in[15];
    float* out = (float*)d_out;

    const int n = in_sizes[0] / 128;
    const int E = in_sizes[1] / 2;

    // fork: CSR build on g_s1, GEMM1 on main stream
    cudaEventRecord(g_ef, 0);
    cudaStreamWaitEvent(g_s1, g_ef, 0);

    const int n4 = (n + 3) / 4;
    k_zero   <<<(n4 + 255) / 256, 256, 0, g_s1>>>(n4);
    k_hist   <<<(E + 255) / 256, 256, 0, g_s1>>>(ei, E, n);
    k_scan   <<<1, 1024, 0, g_s1>>>(n);
    k_scatter<<<(E + 255) / 256, 256, 0, g_s1>>>(ei, E, n);
    cudaEventRecord(g_ej, g_s1);

    const int gb = (n + 127) / 128;
    k_gemm_dual<128, 128><<<gb, 256>>>(x, -1, W1_1, W1_2, 0, 1, n);

    // join
    cudaStreamWaitEvent(0, g_ej, 0);

    const int pb64 = (n * 16 + 255) / 256;
    const int pb32 = (n * 8 + 255) / 256;
    const int pbh  = (n + 7) / 8;

    k_prop<64, false><<<pb64, 256>>>(1, nullptr, 0, 2, n);  // C = P(B) + A
    k_prop<64, true ><<<pb64, 256>>>(2, b1, -1, 0, n);      // A = relu(P(C)+b1) = h1

    k_gemm_dual<64, 64><<<gb, 256>>>(nullptr, 0, W2_1, W2_2, 1, 2, n);
    k_prop<32, false><<<pb32, 256>>>(2, nullptr, 1, 0, n);  // A = P(C) + B

    k_prop_heads<<<pbh, 256>>>(0, b2, Wp1, bp1, Wp2, bp2, Wc1, bc1, Wc2, bc2, out, n);
}